// round 5
// baseline (speedup 1.0000x reference)
#include <cuda_runtime.h>
#include <cuda_bf16.h>
#include <math.h>

// out[d,l]: l==0 -> h0[d]; l>=1 -> sum_k Re(R[k,d]*p[k,d]^(l-1))
// a_t = c1*a_{t-1} - r^2*a_{t-2}; c1 = 2 r cos(theta).
// Kernel A: per-(pole, 4-chunk segment) seeding (no fp64, 1 sincos).
// Kernel B: packed f32x2 recurrence, k-group loads software-pipelined.

#define CHUNK 32
#define MAXD  1024
#define MAXK  32
#define MAXBX 128          // supports L <= 4096
#define SEGC  4            // chunks per seed thread

__device__ float2 g_cc  [MAXK * MAXD];                // (c1, -r^2)
__device__ float2 g_seed[MAXBX * MAXK * MAXD];        // (a0, a1) per (bx,k,d)

typedef unsigned long long u64p;

__device__ __forceinline__ u64p pk2(float lo, float hi) {
    u64p r; asm("mov.b64 %0, {%1, %2};" : "=l"(r) : "f"(lo), "f"(hi)); return r;
}
__device__ __forceinline__ void upk2(u64p v, float& lo, float& hi) {
    asm("mov.b64 {%0, %1}, %2;" : "=f"(lo), "=f"(hi) : "l"(v));
}
__device__ __forceinline__ u64p mul2(u64p a, u64p b) {
    u64p r; asm("mul.rn.f32x2 %0, %1, %2;" : "=l"(r) : "l"(a), "l"(b)); return r;
}
__device__ __forceinline__ u64p add2(u64p a, u64p b) {
    u64p r; asm("add.rn.f32x2 %0, %1, %2;" : "=l"(r) : "l"(a), "l"(b)); return r;
}
__device__ __forceinline__ u64p fma2(u64p a, u64p b, u64p c) {
    u64p r; asm("fma.rn.f32x2 %0, %1, %2, %3;" : "=l"(r) : "l"(a), "l"(b), "l"(c)); return r;
}

// ---------------- Kernel A: seeds ----------------
__global__ void lh_seed_kernel(
    const float* __restrict__ rr, const float* __restrict__ th,
    const float* __restrict__ Rre, const float* __restrict__ Rim,
    int D, int K, int NBX)
{
    const int KD = K * D;
    const int gi = blockIdx.x * blockDim.x + threadIdx.x;
    const int nseg = (NBX + SEGC - 1) / SEGC;
    if (gi >= KD * nseg) return;
    const int i   = gi % KD;      // pole index (coalesced)
    const int seg = gi / KD;

    const float r  = rr[i];
    const float t_ = th[i];
    const float Ar = Rre[i];
    const float Ai = Rim[i];

    float st, ct;
    sincosf(t_, &st, &ct);
    const float pre = r * ct;
    const float pim = r * st;

    if (seg == 0) g_cc[i] = make_float2(2.0f * pre, -(r * r));
    const float invr2 = 1.0f / (r * r);

    // q = p^CHUNK (5 squarings)
    float qr = pre, qi = pim;
#pragma unroll
    for (int s = 0; s < 5; ++s) {
        float nr = fmaf(qr, qr, -qi * qi);
        float ni = 2.0f * qr * qi;
        qr = nr; qi = ni;
    }
    // q4 = q^SEGC (2 squarings)
    float q4r = qr, q4i = qi;
#pragma unroll
    for (int s = 0; s < 2; ++s) {
        float nr = fmaf(q4r, q4r, -q4i * q4i);
        float ni = 2.0f * q4r * q4i;
        q4r = nr; q4i = ni;
    }
    // w = q4^seg, binary powering (seg < 32)
    float wr = 1.0f, wi = 0.0f;
    {
        float br = q4r, bi = q4i;
        int e = seg;
#pragma unroll
        for (int b = 0; b < 5; ++b) {
            if (e & 1) {
                float nr = fmaf(wr, br, -wi * bi);
                float ni = fmaf(wr, bi,  wi * br);
                wr = nr; wi = ni;
            }
            e >>= 1;
            float sr = fmaf(br, br, -bi * bi);
            float si = 2.0f * br * bi;
            br = sr; bi = si;
        }
    }

    // emit seeds for chunks bx = seg*SEGC + j; w = p^(CHUNK*bx)
#pragma unroll
    for (int j = 0; j < SEGC; ++j) {
        int bx = seg * SEGC + j;
        if (bx < NBX) {
            float zr = fmaf(Ar, wr, -Ai * wi);             // a(CHUNK*bx)
            float zi = fmaf(Ar, wi,  Ai * wr);
            float a1 = zr;
            float a0 = fmaf(zr, pre, zi * pim) * invr2;    // a(CHUNK*bx - 1)
            g_seed[(size_t)bx * KD + i] = make_float2(a0, a1);
        }
        float nr = fmaf(wr, qr, -wi * qi);
        float ni = fmaf(wr, qi,  wi * qr);
        wr = nr; wi = ni;
    }
}

// ---------------- Kernel B: recurrence ----------------
// Block 64 thr = 2 warps; d-tile 32 (lane); l-chunk 32 (blockIdx.x).
// Warp w: k in [w*K/2,(w+1)*K/2), groups of 4 -> two packed chains.
// Next group's loads issued before current group's compute (latency hidden).
__global__ __launch_bounds__(64, 8) void lh_recur_kernel(
    const float* __restrict__ h0, float* __restrict__ out,
    int D, int L, int K)
{
    const int bx   = blockIdx.x;
    const int l0   = bx * CHUNK;
    const int d0   = blockIdx.y * 32;
    const int lane = threadIdx.x & 31;
    const int wid  = threadIdx.x >> 5;
    const int d    = d0 + lane;
    const int KD   = K * D;

    __shared__ float tile[2][32][CHUNK + 1];

    u64p acc[CHUNK];
    const u64p z = pk2(0.0f, 0.0f);
#pragma unroll
    for (int i = 0; i < CHUNK; ++i) acc[i] = z;

    const int kbeg = wid * (K >> 1);
    const int kend = kbeg + (K >> 1);
    const float2* __restrict__ cc   = g_cc;
    const float2* __restrict__ seed = &g_seed[(size_t)bx * KD];

    float2 ccn[4], sdn[4];
#pragma unroll
    for (int u = 0; u < 4; ++u) {
        const int idx = (kbeg + u) * D + d;
        ccn[u] = cc[idx];
        sdn[u] = seed[idx];
    }

    for (int kg = kbeg; kg < kend; kg += 4) {
        float2 c[4], s[4];
#pragma unroll
        for (int u = 0; u < 4; ++u) { c[u] = ccn[u]; s[u] = sdn[u]; }

        // prefetch next group (wrap to kbeg on last; harmless dummy)
        const int kn = (kg + 4 < kend) ? kg + 4 : kbeg;
#pragma unroll
        for (int u = 0; u < 4; ++u) {
            const int idx = (kn + u) * D + d;
            ccn[u] = cc[idx];
            sdn[u] = seed[idx];
        }

        u64p C1_0 = pk2(c[0].x, c[1].x);
        u64p C1_1 = pk2(c[2].x, c[3].x);
        u64p N2_0 = pk2(c[0].y, c[1].y);
        u64p N2_1 = pk2(c[2].y, c[3].y);
        u64p A0_0 = pk2(s[0].x, s[1].x);
        u64p A0_1 = pk2(s[2].x, s[3].x);
        u64p A1_0 = pk2(s[0].y, s[1].y);
        u64p A1_1 = pk2(s[2].y, s[3].y);

        acc[0] = add2(acc[0], add2(A0_0, A0_1));
        acc[1] = add2(acc[1], add2(A1_0, A1_1));

        // software-pipelined accumulate: pair-sum S lands one iter late.
        u64p S = z;
#pragma unroll
        for (int i = 2; i < CHUNK; ++i) {
            u64p m0 = mul2(N2_0, A0_0);
            u64p m1 = mul2(N2_1, A0_1);
            u64p n0 = fma2(C1_0, A1_0, m0);
            u64p n1 = fma2(C1_1, A1_1, m1);
            if (i > 2) acc[i - 1] = add2(acc[i - 1], S);
            S = add2(n0, n1);
            A0_0 = A1_0; A1_0 = n0;
            A0_1 = A1_1; A1_1 = n1;
        }
        acc[CHUNK - 1] = add2(acc[CHUNK - 1], S);
    }

#pragma unroll
    for (int i = 0; i < CHUNK; ++i) {
        float lo, hi;
        upk2(acc[i], lo, hi);
        tile[wid][lane][i] = lo + hi;
    }
    __syncthreads();

    const int total = 32 * CHUNK;
    for (int j = threadIdx.x; j < total; j += 64) {
        int row = j >> 5;            // / CHUNK
        int col = j & (CHUNK - 1);   // % CHUNK
        int l = l0 + col;
        float v = tile[0][row][col] + tile[1][row][col];
        if (l0 == 0 && col == 0) v = h0[d0 + row];
        if (l < L) out[(size_t)(d0 + row) * L + l] = v;
    }
}

extern "C" void kernel_launch(void* const* d_in, const int* in_sizes, int n_in,
                              void* d_out, int out_size)
{
    const float* rr  = (const float*)d_in[0];
    const float* th  = (const float*)d_in[1];
    const float* Rre = (const float*)d_in[2];
    const float* Rim = (const float*)d_in[3];
    const float* h0  = (const float*)d_in[4];
    float* out = (float*)d_out;

    const int D = in_sizes[4];
    const int K = in_sizes[0] / D;
    const int L = out_size / D;
    const int NBX = (L + CHUNK - 1) / CHUNK;
    const int nseg = (NBX + SEGC - 1) / SEGC;

    const int na = K * D * nseg;
    lh_seed_kernel<<<(na + 255) / 256, 256>>>(rr, th, Rre, Rim, D, K, NBX);

    dim3 grid(NBX, D / 32);
    lh_recur_kernel<<<grid, 64>>>(h0, out, D, L, K);
}